// round 4
// baseline (speedup 1.0000x reference)
#include <cuda_runtime.h>
#include <math.h>

#define Bb 512
#define Nn 1024
#define Pp 1024
#define Kk 1024
#define Tt 32
#define EPSV 1e-10f

// scratch (no allocations allowed)
__device__ float g_a[Bb * Nn];      // relu activations, row-major [B,N]
__device__ float g_asigT[Nn * Bb];  // sigmoid activations, TRANSPOSED [N,B]
__device__ float g_acc[4];          // 0: recon sq-sum, 1: entropy sum, 2: decay sq-sum

// smem: double-buffered As[2][16][68] + Bs[2][16][64]; reused as 64x65 transpose tile
#define AS_STRIDE 68
#define SMEM_FLOATS (2 * 16 * AS_STRIDE + 2 * 16 * 64)

// ---------------------------------------------------------------------------
// GEMM1: a = relu(x @ w_enc + b_enc); a_sigT = 2/(1+exp(-a)) - 1 (transposed,
// staged through smem for coalesced stores)
// 64x64 tile, 256 threads, 4x4 per thread, BK=16, smem double buffer
// ---------------------------------------------------------------------------
__global__ __launch_bounds__(256) void gemm_enc(const float* __restrict__ X,
                                                const float* __restrict__ W,
                                                const float* __restrict__ bias) {
    __shared__ __align__(16) float smemraw[SMEM_FLOATS];
    float (*As)[16][AS_STRIDE] = (float (*)[16][AS_STRIDE])smemraw;
    float (*Bs)[16][64] = (float (*)[16][64])(smemraw + 2 * 16 * AS_STRIDE);
    int t = threadIdx.x;
    if (blockIdx.x == 0 && blockIdx.y == 0 && t < 4) g_acc[t] = 0.f;
    int m0 = blockIdx.y * 64, n0 = blockIdx.x * 64;
    int arow = t >> 2, acol = (t & 3) << 2;
    int brow = t >> 4, bcol = (t & 15) << 2;
    int ry = (t >> 4) << 2, rx = (t & 15) << 2;
    float acc[4][4] = {};
    const float* ap = X + (m0 + arow) * Kk + acol;
    const float* bp = W + brow * Nn + n0 + bcol;
    float4 av = *(const float4*)ap;
    float4 bv = *(const float4*)bp;
    As[0][acol + 0][arow] = av.x; As[0][acol + 1][arow] = av.y;
    As[0][acol + 2][arow] = av.z; As[0][acol + 3][arow] = av.w;
    *(float4*)(&Bs[0][brow][bcol]) = bv;
    __syncthreads();
    for (int k0 = 0; k0 < Kk; k0 += 16) {
        int cur = (k0 >> 4) & 1, nxt = cur ^ 1;
        bool more = (k0 + 16 < Kk);
        if (more) {
            av = *(const float4*)(ap + k0 + 16);
            bv = *(const float4*)(bp + (k0 + 16) * Nn);
        }
#pragma unroll
        for (int k = 0; k < 16; k++) {
            float4 a4 = *(float4*)(&As[cur][k][ry]);
            float4 b4 = *(float4*)(&Bs[cur][k][rx]);
            float am[4] = {a4.x, a4.y, a4.z, a4.w};
            float bn[4] = {b4.x, b4.y, b4.z, b4.w};
#pragma unroll
            for (int i = 0; i < 4; i++)
#pragma unroll
                for (int j = 0; j < 4; j++)
                    acc[i][j] = fmaf(am[i], bn[j], acc[i][j]);
        }
        if (more) {
            As[nxt][acol + 0][arow] = av.x; As[nxt][acol + 1][arow] = av.y;
            As[nxt][acol + 2][arow] = av.z; As[nxt][acol + 3][arow] = av.w;
            *(float4*)(&Bs[nxt][brow][bcol]) = bv;
        }
        __syncthreads();
    }
    // epilogue: relu -> g_a (float4), a_sig -> smem transpose tile
    float* tsh = smemraw;  // [n_local][m_local] 64x65
    float4 bias4 = *(const float4*)(bias + n0 + rx);
    float bb[4] = {bias4.x, bias4.y, bias4.z, bias4.w};
#pragma unroll
    for (int i = 0; i < 4; i++) {
        int m = m0 + ry + i;
        float4 va;
        float aa[4];
#pragma unroll
        for (int j = 0; j < 4; j++) {
            float v = acc[i][j] + bb[j];
            float a = fmaxf(v, 0.f);
            aa[j] = a;
            float e = __expf(-a);
            tsh[(rx + j) * 65 + ry + i] = __fdividef(2.f, 1.f + e) - 1.f;
        }
        va.x = aa[0]; va.y = aa[1]; va.z = aa[2]; va.w = aa[3];
        *(float4*)(g_a + m * Nn + n0 + rx) = va;
    }
    __syncthreads();
    // coalesced transposed store: thread -> (column n_local, 16 consecutive m)
    int nl = t >> 2, mb = (t & 3) << 4;
    float* dst = g_asigT + (n0 + nl) * Bb + m0 + mb;
    const float* src = tsh + nl * 65 + mb;
#pragma unroll
    for (int s = 0; s < 16; s += 4)
        *(float4*)(dst + s) = make_float4(src[s], src[s + 1], src[s + 2], src[s + 3]);
}

// ---------------------------------------------------------------------------
// GEMM2: x_hat = a @ w_dec + b_dec ; accumulate sum((x-x_hat)^2)
// ---------------------------------------------------------------------------
__global__ __launch_bounds__(256) void gemm_dec(const float* __restrict__ W,
                                                const float* __restrict__ bias,
                                                const float* __restrict__ X,
                                                float* __restrict__ xhat) {
    __shared__ __align__(16) float smemraw[SMEM_FLOATS];
    float (*As)[16][AS_STRIDE] = (float (*)[16][AS_STRIDE])smemraw;
    float (*Bs)[16][64] = (float (*)[16][64])(smemraw + 2 * 16 * AS_STRIDE);
    int t = threadIdx.x;
    int m0 = blockIdx.y * 64, n0 = blockIdx.x * 64;
    int arow = t >> 2, acol = (t & 3) << 2;
    int brow = t >> 4, bcol = (t & 15) << 2;
    int ry = (t >> 4) << 2, rx = (t & 15) << 2;
    float acc[4][4] = {};
    const float* ap = g_a + (m0 + arow) * Nn + acol;
    const float* bp = W + brow * Pp + n0 + bcol;
    float4 av = *(const float4*)ap;
    float4 bv = *(const float4*)bp;
    As[0][acol + 0][arow] = av.x; As[0][acol + 1][arow] = av.y;
    As[0][acol + 2][arow] = av.z; As[0][acol + 3][arow] = av.w;
    *(float4*)(&Bs[0][brow][bcol]) = bv;
    __syncthreads();
    for (int k0 = 0; k0 < Nn; k0 += 16) {
        int cur = (k0 >> 4) & 1, nxt = cur ^ 1;
        bool more = (k0 + 16 < Nn);
        if (more) {
            av = *(const float4*)(ap + k0 + 16);
            bv = *(const float4*)(bp + (k0 + 16) * Pp);
        }
#pragma unroll
        for (int k = 0; k < 16; k++) {
            float4 a4 = *(float4*)(&As[cur][k][ry]);
            float4 b4 = *(float4*)(&Bs[cur][k][rx]);
            float am[4] = {a4.x, a4.y, a4.z, a4.w};
            float bn[4] = {b4.x, b4.y, b4.z, b4.w};
#pragma unroll
            for (int i = 0; i < 4; i++)
#pragma unroll
                for (int j = 0; j < 4; j++)
                    acc[i][j] = fmaf(am[i], bn[j], acc[i][j]);
        }
        if (more) {
            As[nxt][acol + 0][arow] = av.x; As[nxt][acol + 1][arow] = av.y;
            As[nxt][acol + 2][arow] = av.z; As[nxt][acol + 3][arow] = av.w;
            *(float4*)(&Bs[nxt][brow][bcol]) = bv;
        }
        __syncthreads();
    }
    float lsum = 0.f;
    float4 bias4 = *(const float4*)(bias + n0 + rx);
    float bb[4] = {bias4.x, bias4.y, bias4.z, bias4.w};
#pragma unroll
    for (int i = 0; i < 4; i++) {
        int m = m0 + ry + i;
        float4 xv = *(const float4*)(X + m * Pp + n0 + rx);
        float xm[4] = {xv.x, xv.y, xv.z, xv.w};
        float vv[4];
#pragma unroll
        for (int j = 0; j < 4; j++) {
            float v = acc[i][j] + bb[j];
            vv[j] = v;
            float d = xm[j] - v;
            lsum = fmaf(d, d, lsum);
        }
        *(float4*)(xhat + m * Pp + n0 + rx) = make_float4(vv[0], vv[1], vv[2], vv[3]);
    }
#pragma unroll
    for (int o = 16; o > 0; o >>= 1) lsum += __shfl_xor_sync(~0u, lsum, o);
    __shared__ float red[8];
    if ((t & 31) == 0) red[t >> 5] = lsum;
    __syncthreads();
    if (t == 0) {
        float tot = 0.f;
#pragma unroll
        for (int i = 0; i < 8; i++) tot += red[i];
        atomicAdd(&g_acc[0], tot);
    }
}

// ---------------------------------------------------------------------------
// MLE: per-neuron 15-step gradient ascent on thetas + entropy.
// One warp per neuron; 16 samples/lane in registers; exact-0 / exact-1
// clusters handled analytically; residual scatter uses 4-way replicated,
// bank-padded G.
// ---------------------------------------------------------------------------
__global__ __launch_bounds__(128) void mle_kernel(const float* __restrict__ thetas,
                                                  const float* __restrict__ centers,
                                                  float* __restrict__ ent_out) {
    __shared__ float s_pi[4][32];
    __shared__ float s_G[4][4 * 33];
    __shared__ float s_c[32];
    int tid = threadIdx.x;
    int warp = tid >> 5, lane = tid & 31;
    if (tid < 32) s_c[tid] = centers[tid];
    __syncthreads();
    int n = blockIdx.x * 4 + warp;
    float c0 = s_c[0];
    float invw = __fdividef(1.0f, s_c[1] - s_c[0]);

    const float* col = g_asigT + n * Bb;
    int t0[16];
    float w0[16], w1[16];
    unsigned zbits = 0, obits = 0;
    int zc = 0, oc = 0;
#pragma unroll
    for (int i = 0; i < 16; i++) {
        float as = col[i * 32 + lane];
        if (as == 0.f) { zbits |= 1u << i; zc++; }
        else if (as == 1.f) { obits |= 1u << i; oc++; }
        float xf = (as - c0) * invw;
        int tt = (int)floorf(xf);
        tt = min(max(tt, 0), 30);
        t0[i] = tt;
        w0[i] = fmaxf(0.f, 1.f - fabsf(as - s_c[tt]) * invw);
        w1[i] = fmaxf(0.f, 1.f - fabsf(as - s_c[tt + 1]) * invw);
    }
    int ztot = zc, otot = oc;
#pragma unroll
    for (int o = 16; o > 0; o >>= 1) {
        ztot += __shfl_xor_sync(~0u, ztot, o);
        otot += __shfl_xor_sync(~0u, otot, o);
    }
    float w0z = fmaxf(0.f, 1.f - fabsf(s_c[15]) * invw);
    float w1z = fmaxf(0.f, 1.f - fabsf(s_c[16]) * invw);
    float w0o = fmaxf(0.f, 1.f - fabsf(1.f - s_c[30]) * invw);
    float w1o = fmaxf(0.f, 1.f - fabsf(1.f - s_c[31]) * invw);
    float zf = (float)ztot, of = (float)otot;

    float th = thetas[n * Tt + lane];
    float* pi = s_pi[warp];
    float* G = s_G[warp];
    int rep = (lane & 3) * 33;
    unsigned skip = zbits | obits;

    for (int step = 0; step < 15; step++) {
        float m = th;
#pragma unroll
        for (int o = 16; o > 0; o >>= 1) m = fmaxf(m, __shfl_xor_sync(~0u, m, o));
        float e = __expf(th - m);
        float sum = e;
#pragma unroll
        for (int o = 16; o > 0; o >>= 1) sum += __shfl_xor_sync(~0u, sum, o);
        float p_l = __fdividef(e, sum);
        pi[lane] = p_l;
        G[0 * 33 + lane] = 0.f; G[1 * 33 + lane] = 0.f;
        G[2 * 33 + lane] = 0.f; G[3 * 33 + lane] = 0.f;
        __syncwarp();

        float s_acc = 0.f;
        if (lane == 0 && ztot > 0) {
            float pz = w0z * pi[15] + w1z * pi[16];
            float rz = __fdividef(1.f, pz + EPSV);
            atomicAdd(&G[0 * 33 + 15], zf * w0z * rz);
            atomicAdd(&G[0 * 33 + 16], zf * w1z * rz);
            s_acc += zf * pz * rz;
        }
        if (lane == 1 && otot > 0) {
            float po = w0o * pi[30] + w1o * pi[31];
            float ro = __fdividef(1.f, po + EPSV);
            atomicAdd(&G[1 * 33 + 30], of * w0o * ro);
            atomicAdd(&G[1 * 33 + 31], of * w1o * ro);
            s_acc += of * po * ro;
        }
#pragma unroll
        for (int i = 0; i < 16; i++) {
            if (!((skip >> i) & 1u)) {
                float p = w0[i] * pi[t0[i]] + w1[i] * pi[t0[i] + 1];
                float r = __fdividef(1.f, p + EPSV);
                atomicAdd(&G[rep + t0[i]], w0[i] * r);
                atomicAdd(&G[rep + t0[i] + 1], w1[i] * r);
                s_acc = fmaf(p, r, s_acc);
            }
        }
#pragma unroll
        for (int o = 16; o > 0; o >>= 1) s_acc += __shfl_xor_sync(~0u, s_acc, o);
        __syncwarp();
        float g = G[0 * 33 + lane] + G[1 * 33 + lane] +
                  G[2 * 33 + lane] + G[3 * 33 + lane];
        th += 0.01f * (p_l * (g - s_acc));
        __syncwarp();
    }

    float m = th;
#pragma unroll
    for (int o = 16; o > 0; o >>= 1) m = fmaxf(m, __shfl_xor_sync(~0u, m, o));
    float e = __expf(th - m);
    float sum = e;
#pragma unroll
    for (int o = 16; o > 0; o >>= 1) sum += __shfl_xor_sync(~0u, sum, o);
    pi[lane] = __fdividef(e, sum);
    __syncwarp();

    float ent = 0.f;
    if (lane == 0 && ztot > 0) {
        float pz = w0z * pi[15] + w1z * pi[16];
        ent -= zf * pz * __logf(pz + EPSV);
    }
    if (lane == 1 && otot > 0) {
        float po = w0o * pi[30] + w1o * pi[31];
        ent -= of * po * __logf(po + EPSV);
    }
#pragma unroll
    for (int i = 0; i < 16; i++) {
        if (!((skip >> i) & 1u)) {
            float p = w0[i] * pi[t0[i]] + w1[i] * pi[t0[i] + 1];
            ent -= p * __logf(p + EPSV);
        }
    }
#pragma unroll
    for (int o = 16; o > 0; o >>= 1) ent += __shfl_xor_sync(~0u, ent, o);
    if (lane == 0) {
        ent_out[n] = ent;
        atomicAdd(&g_acc[1], ent);
    }
}

// ---------------------------------------------------------------------------
// decay: sum(w_enc^2) + sum(w_dec^2), vectorized
// ---------------------------------------------------------------------------
__global__ __launch_bounds__(256) void decay_kernel(const float* __restrict__ we,
                                                    const float* __restrict__ wd) {
    float s = 0.f;
    const float4* we4 = (const float4*)we;
    const float4* wd4 = (const float4*)wd;
    int nv = (Nn * Pp) / 4;
    for (int i = blockIdx.x * blockDim.x + threadIdx.x; i < nv;
         i += gridDim.x * blockDim.x) {
        float4 a = we4[i];
        s = fmaf(a.x, a.x, s); s = fmaf(a.y, a.y, s);
        s = fmaf(a.z, a.z, s); s = fmaf(a.w, a.w, s);
        float4 b = wd4[i];
        s = fmaf(b.x, b.x, s); s = fmaf(b.y, b.y, s);
        s = fmaf(b.z, b.z, s); s = fmaf(b.w, b.w, s);
    }
#pragma unroll
    for (int o = 16; o > 0; o >>= 1) s += __shfl_xor_sync(~0u, s, o);
    __shared__ float red[8];
    if ((threadIdx.x & 31) == 0) red[threadIdx.x >> 5] = s;
    __syncthreads();
    if (threadIdx.x == 0) {
        float tot = 0.f;
#pragma unroll
        for (int i = 0; i < 8; i++) tot += red[i];
        atomicAdd(&g_acc[2], tot);
    }
}

__global__ void finalize_kernel(float* __restrict__ out) {
    out[Bb * Pp + Nn] = (0.5f / (float)Bb) * g_acc[0] + 0.01f * g_acc[1] +
                        0.00025f * g_acc[2];
}

extern "C" void kernel_launch(void* const* d_in, const int* in_sizes, int n_in,
                              void* d_out, int out_size) {
    const float* x   = (const float*)d_in[0];
    const float* we  = (const float*)d_in[1];
    const float* be  = (const float*)d_in[2];
    const float* wd  = (const float*)d_in[3];
    const float* bd  = (const float*)d_in[4];
    const float* th  = (const float*)d_in[5];
    const float* cen = (const float*)d_in[6];
    float* out = (float*)d_out;

    gemm_enc<<<dim3(Nn / 64, Bb / 64), 256>>>(x, we, be);
    mle_kernel<<<Nn / 4, 128>>>(th, cen, out + Bb * Pp);
    decay_kernel<<<512, 256>>>(we, wd);
    gemm_dec<<<dim3(Pp / 64, Bb / 64), 256>>>(wd, bd, x, out);
    finalize_kernel<<<1, 1>>>(out);
}